// round 3
// baseline (speedup 1.0000x reference)
#include <cuda_runtime.h>
#include <cuda_bf16.h>
#include <cstdint>
#include <cstddef>

// ---------------------------------------------------------------------------
// Problem: B=64, T=512, K=8, H=256 (4H=1024), HID1=100, HID2=128, OUT=24
// Inputs (metadata order):
//  0 x(64,512,8)  1 Wih0(1024,8) 2 Whh0(1024,256) 3 bih0 4 bhh0
//  5 Wih1(1024,256) 6 Whh1(1024,256) 7 bih1 8 bhh1
//  9 Wl1(100,256) 10 Wr1(100,256) 11 b1(100)
// 12 Wl2(128,100) 13 Wr2(128,100) 14 b2(128)
// 15 Wfc1(8,64,128) 16 bfc1(8,64) 17 Wfc2(8,24,64) 18 bfc2(8,24)
// Output: pred (8,64,24) float32
// ---------------------------------------------------------------------------

// Scratch (static device globals: allocation-free)
__device__ float g_G[512u * 64u * 1024u];   // gate pre-activations (reused L0/L1)
__device__ float g_h0[512u * 64u * 256u];   // layer-0 h, time-major [t][b][k]
__device__ float g_h1[512u * 64u * 256u];   // layer-1 h, time-major [t][b][k]
__device__ float g_hsum[64 * 256];          // sum_t h1
__device__ float g_a[64 * 128];             // m@Wl1.T + b1  (100 used)
__device__ float g_ypart[8 * 64 * 128];     // partial sums of y over t-chunks
__device__ float g_y511[64 * 128];          // y at t=511 (100 used)
__device__ float g_s[64 * 128];             // s = h2[:, -1, :]

__device__ __forceinline__ void cluster_sync_asm() {
    asm volatile("barrier.cluster.arrive.aligned;" ::: "memory");
    asm volatile("barrier.cluster.wait.aligned;" ::: "memory");
}

__device__ __forceinline__ void st_dsmem(uint32_t laddr, uint32_t rk, float v) {
    uint32_t ra;
    asm volatile("mapa.shared::cluster.u32 %0, %1, %2;" : "=r"(ra) : "r"(laddr), "r"(rk));
    asm volatile("st.shared::cluster.f32 [%0], %1;" :: "r"(ra), "f"(v) : "memory");
}

__device__ __forceinline__ float sigf(float x) { return 1.0f / (1.0f + __expf(-x)); }

// ---------------------------------------------------------------------------
// Phase A: G0[t][b][row] = (bih0+bhh0)[row] + sum_{k<8} x[b][t][k]*Wih0[row][k]
// grid 32768 (t*64+... actually bid = t*64? we use b = bid&63, t = bid>>6), 256 thr
// ---------------------------------------------------------------------------
__global__ void __launch_bounds__(256) phaseA_kernel(
    const float* __restrict__ x, const float* __restrict__ Wih0,
    const float* __restrict__ bih0, const float* __restrict__ bhh0,
    float* __restrict__ G)
{
    int bid = blockIdx.x;
    int b = bid & 63;
    int t = bid >> 6;
    __shared__ float xs[8];
    if (threadIdx.x < 8)
        xs[threadIdx.x] = x[((size_t)b * 512 + t) * 8 + threadIdx.x];
    __syncthreads();
    int row = threadIdx.x;
    size_t gb = ((size_t)t * 64 + b) * 1024;
#pragma unroll
    for (int g = 0; g < 4; g++) {
        int r = row + g * 256;
        const float* wr = Wih0 + (size_t)r * 8;
        float acc = bih0[r] + bhh0[r];
#pragma unroll
        for (int k = 0; k < 8; k++) acc = fmaf(wr[k], xs[k], acc);
        G[gb + r] = acc;
    }
}

// ---------------------------------------------------------------------------
// LSTM recurrence. 16 clusters x 8 CTAs (grid 128), 512 threads.
// Cluster cl owns batch rows [4cl, 4cl+4). CTA rank r owns hidden units
// [32r, 32r+32) => gate rows {g*256 + 32r + u}. Whh slice in registers
// (64 floats/thread). h exchanged via DSMEM push + 1 cluster.sync per step
// (double-buffered h in SMEM). c-state in registers of threads 0..127.
// ---------------------------------------------------------------------------
__global__ void __cluster_dims__(8, 1, 1) __launch_bounds__(512, 1)
lstm_recur_kernel(const float* __restrict__ G, const float* __restrict__ Whh,
                  float* __restrict__ hout, float* __restrict__ hsum, int dosum)
{
    // padded h layout: hk(k) = k + (k>>6)*4  -> kc-chunks start at 0,272,544,816 B
    __shared__ float hbuf[2][4][272];
    __shared__ float gsm[4][4][33];   // [gate][b][u]

    int tid = threadIdx.x;
    int rank = blockIdx.x & 7;
    int cl = blockIdx.x >> 3;
    int row_local = tid >> 2;         // 0..127
    int kc = tid & 3;                 // k-chunk of 64
    int gate = row_local >> 5;        // 0..3 : i,f,g,o
    int u = row_local & 31;
    int grow = gate * 256 + rank * 32 + u;

    // weights into registers (64 floats = 16 float4)
    float w[64];
    {
        const float4* wp4 = (const float4*)(Whh + (size_t)grow * 256 + kc * 64);
        float4* w4 = (float4*)w;
#pragma unroll
        for (int i = 0; i < 16; i++) w4[i] = wp4[i];
    }

    // zero read buffer 0 (local only; peers never touch our buf 0 before t=0 reads)
    for (int i = tid; i < 4 * 272; i += 512) (&hbuf[0][0][0])[i] = 0.0f;

    int bb = tid >> 5;                // update-thread batch (tid<128)
    int ub = tid & 31;                // update-thread unit
    float c = 0.0f, hs = 0.0f;
    uint32_t push_addr0 = 0;
    {
        int k = rank * 32 + ub;
        int hk = k + ((k >> 6) << 2);
        push_addr0 = (uint32_t)__cvta_generic_to_shared(&hbuf[0][bb][hk]);
    }
    uint32_t buf_stride = (uint32_t)((char*)&hbuf[1][0][0] - (char*)&hbuf[0][0][0]);
    __syncthreads();

    int cur = 0;
    for (int t = 0; t < 512; t++) {
        // prefetch gate input (independent of h; issues early)
        const float* gp = G + ((size_t)t * 64 + cl * 4) * 1024 + grow;
        float gin0 = gp[0], gin1 = gp[1024], gin2 = gp[2048], gin3 = gp[3072];

        float acc[4];
#pragma unroll
        for (int b = 0; b < 4; b++) {
            const float4* hp = (const float4*)&hbuf[cur][b][kc * 68];
            float a0 = 0.0f, a1 = 0.0f;
#pragma unroll
            for (int q = 0; q < 8; q++) {
                float4 h4 = hp[2 * q];
                a0 = fmaf(w[8 * q + 0], h4.x, a0);
                a0 = fmaf(w[8 * q + 1], h4.y, a0);
                a0 = fmaf(w[8 * q + 2], h4.z, a0);
                a0 = fmaf(w[8 * q + 3], h4.w, a0);
                float4 h5 = hp[2 * q + 1];
                a1 = fmaf(w[8 * q + 4], h5.x, a1);
                a1 = fmaf(w[8 * q + 5], h5.y, a1);
                a1 = fmaf(w[8 * q + 6], h5.z, a1);
                a1 = fmaf(w[8 * q + 7], h5.w, a1);
            }
            acc[b] = a0 + a1;
        }
#pragma unroll
        for (int b = 0; b < 4; b++) {
            float v = acc[b];
            v += __shfl_xor_sync(0xffffffffu, v, 1);
            v += __shfl_xor_sync(0xffffffffu, v, 2);
            acc[b] = v;
        }
        if (kc == 0) {
            gsm[gate][0][u] = acc[0] + gin0;
            gsm[gate][1][u] = acc[1] + gin1;
            gsm[gate][2][u] = acc[2] + gin2;
            gsm[gate][3][u] = acc[3] + gin3;
        }
        __syncthreads();

        if (tid < 128) {
            float gi = gsm[0][bb][ub];
            float gf = gsm[1][bb][ub];
            float gg = gsm[2][bb][ub];
            float go = gsm[3][bb][ub];
            c = sigf(gf) * c + sigf(gi) * tanhf(gg);
            float h = sigf(go) * tanhf(c);
            hs += h;
            hout[((size_t)t * 64 + cl * 4 + bb) * 256 + rank * 32 + ub] = h;
            // push h into next buffer of every CTA in the cluster
            uint32_t pa = push_addr0 + (uint32_t)(cur ^ 1) * buf_stride;
#pragma unroll
            for (int r = 0; r < 8; r++) st_dsmem(pa, (uint32_t)r, h);
        }
        cluster_sync_asm();
        cur ^= 1;
    }
    if (dosum && tid < 128)
        hsum[(cl * 4 + bb) * 256 + rank * 32 + ub] = hs;
}

// ---------------------------------------------------------------------------
// fp32 NT GEMM: C[M=32768][N=1024] = A[M][256] @ B[N][256]^T + (bi+bh)[n]
// 64x64 tile, BK=16, 256 threads, 4x4 per thread. grid (16, 512)
// ---------------------------------------------------------------------------
__global__ void __launch_bounds__(256) gemm_nt_kernel(
    const float* __restrict__ A, const float* __restrict__ B,
    const float* __restrict__ bi, const float* __restrict__ bh,
    float* __restrict__ C)
{
    __shared__ float As[16][68];
    __shared__ float Bs[16][68];
    int tid = threadIdx.x;
    int tx = tid & 15, ty = tid >> 4;
    int bm = blockIdx.y * 64, bn = blockIdx.x * 64;
    int lrow = tid >> 2, lkq = tid & 3;

    float acc[4][4] = {};
    for (int kk = 0; kk < 256; kk += 16) {
        float4 av = *(const float4*)(A + (size_t)(bm + lrow) * 256 + kk + lkq * 4);
        float4 bv = *(const float4*)(B + (size_t)(bn + lrow) * 256 + kk + lkq * 4);
        As[lkq * 4 + 0][lrow] = av.x; As[lkq * 4 + 1][lrow] = av.y;
        As[lkq * 4 + 2][lrow] = av.z; As[lkq * 4 + 3][lrow] = av.w;
        Bs[lkq * 4 + 0][lrow] = bv.x; Bs[lkq * 4 + 1][lrow] = bv.y;
        Bs[lkq * 4 + 2][lrow] = bv.z; Bs[lkq * 4 + 3][lrow] = bv.w;
        __syncthreads();
#pragma unroll
        for (int k = 0; k < 16; k++) {
            float4 a4 = *(const float4*)&As[k][tx * 4];
            float4 b4 = *(const float4*)&Bs[k][ty * 4];
            float am[4] = {a4.x, a4.y, a4.z, a4.w};
            float bn4[4] = {b4.x, b4.y, b4.z, b4.w};
#pragma unroll
            for (int i = 0; i < 4; i++)
#pragma unroll
                for (int j = 0; j < 4; j++)
                    acc[i][j] = fmaf(am[i], bn4[j], acc[i][j]);
        }
        __syncthreads();
    }
#pragma unroll
    for (int i = 0; i < 4; i++) {
        size_t row = (size_t)(bm + tx * 4 + i) * 1024 + bn + ty * 4;
#pragma unroll
        for (int j = 0; j < 4; j++) {
            int n = bn + ty * 4 + j;
            C[row + j] = acc[i][j] + bi[n] + bh[n];
        }
    }
}

// ---------------------------------------------------------------------------
// Phase E: m = hsum/512 ; a[b][n] = m[b] . Wl1[n] + b1[n]   (n<100)
// grid 64, block 128
// ---------------------------------------------------------------------------
__global__ void __launch_bounds__(128) phaseE_kernel(
    const float* __restrict__ hsum, const float* __restrict__ Wl1,
    const float* __restrict__ b1, float* __restrict__ a)
{
    int b = blockIdx.x;
    __shared__ float ms[256];
    for (int i = threadIdx.x; i < 256; i += 128)
        ms[i] = hsum[b * 256 + i] * (1.0f / 512.0f);
    __syncthreads();
    int n = threadIdx.x;
    if (n < 100) {
        const float* wr = Wl1 + (size_t)n * 256;
        float acc = b1[n];
        for (int k = 0; k < 256; k++) acc = fmaf(wr[k], ms[k], acc);
        a[b * 128 + n] = acc;
    }
}

// ---------------------------------------------------------------------------
// Phase F: y[b,t,n] = elu(h1[t,b] . Wr1[n] + a[b][n]); accumulate sum_t y per
// t-chunk (deterministic), store y at t=511. grid (8 chunks, 64 b), 512 thr.
// thread: n = tid/4 (<100 active), kc = tid%4 holds Wr1[n][kc*64..+64) in regs
// ---------------------------------------------------------------------------
__global__ void __launch_bounds__(512) phaseF_kernel(
    const float* __restrict__ h1, const float* __restrict__ Wr1,
    const float* __restrict__ a, float* __restrict__ ypart,
    float* __restrict__ y511)
{
    int chunk = blockIdx.x;
    int b = blockIdx.y;
    int tid = threadIdx.x;
    int n = tid >> 2, kc = tid & 3;
    bool act = (n < 100);

    float w[64];
    if (act) {
        const float4* wp4 = (const float4*)(Wr1 + (size_t)n * 256 + kc * 64);
        float4* w4 = (float4*)w;
#pragma unroll
        for (int i = 0; i < 16; i++) w4[i] = wp4[i];
    }
    float ab = act ? a[b * 128 + n] : 0.0f;

    __shared__ float hsm[256];
    float acc = 0.0f;
    for (int tt = 0; tt < 64; tt++) {
        int t = chunk * 64 + tt;
        if (tid < 64)
            ((float4*)hsm)[tid] = ((const float4*)(h1 + ((size_t)t * 64 + b) * 256))[tid];
        __syncthreads();
        float d = 0.0f;
        if (act) {
            const float4* hp = (const float4*)&hsm[kc * 64];
#pragma unroll
            for (int q = 0; q < 16; q++) {
                float4 h4 = hp[q];
                d = fmaf(w[4 * q + 0], h4.x, d);
                d = fmaf(w[4 * q + 1], h4.y, d);
                d = fmaf(w[4 * q + 2], h4.z, d);
                d = fmaf(w[4 * q + 3], h4.w, d);
            }
        }
        d += __shfl_xor_sync(0xffffffffu, d, 1);
        d += __shfl_xor_sync(0xffffffffu, d, 2);
        if (act && kc == 0) {
            float p = d + ab;
            float y = (p > 0.0f) ? p : expm1f(p);
            acc += y;
            if (t == 511) y511[b * 128 + n] = y;
        }
        __syncthreads();
    }
    if (act && kc == 0) ypart[(chunk * 64 + b) * 128 + n] = acc;
}

// ---------------------------------------------------------------------------
// Phase G: m1 = (sum chunks)/512 ; s[b][d] = m1.Wl2[d] + b2[d] + y511.Wr2[d]
// grid 64, block 128
// ---------------------------------------------------------------------------
__global__ void __launch_bounds__(128) phaseG_kernel(
    const float* __restrict__ ypart, const float* __restrict__ y511,
    const float* __restrict__ Wl2, const float* __restrict__ b2,
    const float* __restrict__ Wr2, float* __restrict__ s)
{
    int b = blockIdx.x;
    int tid = threadIdx.x;
    __shared__ float m1[100], yl[100];
    if (tid < 100) {
        float t = 0.0f;
        for (int c2 = 0; c2 < 8; c2++) t += ypart[(c2 * 64 + b) * 128 + tid];
        m1[tid] = t * (1.0f / 512.0f);
        yl[tid] = y511[b * 128 + tid];
    }
    __syncthreads();
    const float* wl = Wl2 + (size_t)tid * 100;
    const float* wr = Wr2 + (size_t)tid * 100;
    float acc = b2[tid];
    for (int n = 0; n < 100; n++) {
        acc = fmaf(m1[n], wl[n], acc);
        acc = fmaf(yl[n], wr[n], acc);
    }
    s[b * 128 + tid] = acc;
}

// ---------------------------------------------------------------------------
// Phase H: z[k,b,o] = relu(s[b].Wfc1[k,o] + bfc1[k,o]);
//          pred[k,b,p] = z[k,b].Wfc2[k,p] + bfc2[k,p]
// grid (8, 64), block 64
// ---------------------------------------------------------------------------
__global__ void __launch_bounds__(64) phaseH_kernel(
    const float* __restrict__ s, const float* __restrict__ Wfc1,
    const float* __restrict__ bfc1, const float* __restrict__ Wfc2,
    const float* __restrict__ bfc2, float* __restrict__ out)
{
    int k = blockIdx.x;
    int b = blockIdx.y;
    int o = threadIdx.x;
    __shared__ float ss[128], zz[64];
    ((float2*)ss)[o] = ((const float2*)(s + b * 128))[o];
    __syncthreads();
    {
        const float* w = Wfc1 + ((size_t)k * 64 + o) * 128;
        float acc = bfc1[k * 64 + o];
        for (int d = 0; d < 128; d++) acc = fmaf(w[d], ss[d], acc);
        zz[o] = (acc > 0.0f) ? acc : 0.0f;
    }
    __syncthreads();
    if (o < 24) {
        const float* w2 = Wfc2 + ((size_t)k * 24 + o) * 64;
        float acc = bfc2[k * 24 + o];
        for (int d = 0; d < 64; d++) acc = fmaf(w2[d], zz[d], acc);
        out[((size_t)k * 64 + b) * 24 + o] = acc;
    }
}

// ---------------------------------------------------------------------------
extern "C" void kernel_launch(void* const* d_in, const int* in_sizes, int n_in,
                              void* d_out, int out_size)
{
    const float* x    = (const float*)d_in[0];
    const float* Wih0 = (const float*)d_in[1];
    const float* Whh0 = (const float*)d_in[2];
    const float* bih0 = (const float*)d_in[3];
    const float* bhh0 = (const float*)d_in[4];
    const float* Wih1 = (const float*)d_in[5];
    const float* Whh1 = (const float*)d_in[6];
    const float* bih1 = (const float*)d_in[7];
    const float* bhh1 = (const float*)d_in[8];
    const float* Wl1  = (const float*)d_in[9];
    const float* Wr1  = (const float*)d_in[10];
    const float* b1   = (const float*)d_in[11];
    const float* Wl2  = (const float*)d_in[12];
    const float* Wr2  = (const float*)d_in[13];
    const float* b2   = (const float*)d_in[14];
    const float* Wfc1 = (const float*)d_in[15];
    const float* bfc1 = (const float*)d_in[16];
    const float* Wfc2 = (const float*)d_in[17];
    const float* bfc2 = (const float*)d_in[18];

    float *G, *h0, *h1, *hsum, *a, *ypart, *y511, *s;
    cudaGetSymbolAddress((void**)&G, g_G);
    cudaGetSymbolAddress((void**)&h0, g_h0);
    cudaGetSymbolAddress((void**)&h1, g_h1);
    cudaGetSymbolAddress((void**)&hsum, g_hsum);
    cudaGetSymbolAddress((void**)&a, g_a);
    cudaGetSymbolAddress((void**)&ypart, g_ypart);
    cudaGetSymbolAddress((void**)&y511, g_y511);
    cudaGetSymbolAddress((void**)&s, g_s);

    // G0 = x @ Wih0.T + bias0
    phaseA_kernel<<<32768, 256>>>(x, Wih0, bih0, bhh0, G);
    // layer-0 recurrence -> h0
    lstm_recur_kernel<<<128, 512>>>(G, Whh0, h0, hsum, 0);
    // G1 = h0 @ Wih1.T + bias1
    gemm_nt_kernel<<<dim3(16, 512), 256>>>(h0, Wih1, bih1, bhh1, G);
    // layer-1 recurrence -> h1, hsum
    lstm_recur_kernel<<<128, 512>>>(G, Whh1, h1, hsum, 1);
    // head
    phaseE_kernel<<<64, 128>>>(hsum, Wl1, b1, a);
    phaseF_kernel<<<dim3(8, 64), 512>>>(h1, Wr1, a, ypart, y511);
    phaseG_kernel<<<64, 128>>>(ypart, y511, Wl2, b2, Wr2, s);
    phaseH_kernel<<<dim3(8, 64), 64>>>(s, Wfc1, bfc1, Wfc2, bfc2, (float*)d_out);
}

// round 6
// speedup vs baseline: 1.0364x; 1.0364x over previous
#include <cuda_runtime.h>
#include <cuda_bf16.h>
#include <cstdint>
#include <cstddef>

// ---------------------------------------------------------------------------
// Problem: B=64, T=512, K=8, H=256 (4H=1024), HID1=100, HID2=128, OUT=24
// Output: pred (8,64,24) float32
// ---------------------------------------------------------------------------

// Scratch (static device globals: allocation-free)
__device__ float g_G[512u * 64u * 1024u];   // gate pre-activations (reused L0/L1)
__device__ float g_h0[512u * 64u * 256u];   // layer-0 h, time-major [t][b][k]
__device__ float g_h1[512u * 64u * 256u];   // layer-1 h, time-major [t][b][k]
__device__ float g_hsum[64 * 256];          // sum_t h1
__device__ float g_a[64 * 128];             // m@Wl1.T + b1  (100 used)
__device__ float g_ypart[8 * 64 * 128];     // partial sums of y over t-chunks
__device__ float g_y511[64 * 128];          // y at t=511 (100 used)
__device__ float g_s[64 * 128];             // s = h2[:, -1, :]

// ---------------------------------------------------------------------------
// PTX helpers
// ---------------------------------------------------------------------------
__device__ __forceinline__ void cluster_sync_asm() {
    asm volatile("barrier.cluster.arrive.aligned;" ::: "memory");
    asm volatile("barrier.cluster.wait.aligned;" ::: "memory");
}

__device__ __forceinline__ void st_dsmem(uint32_t laddr, uint32_t rk, float v) {
    uint32_t ra;
    asm volatile("mapa.shared::cluster.u32 %0, %1, %2;" : "=r"(ra) : "r"(laddr), "r"(rk));
    asm volatile("st.shared::cluster.f32 [%0], %1;" :: "r"(ra), "f"(v) : "memory");
}

__device__ __forceinline__ void mbar_arrive_remote(uint32_t laddr, uint32_t rk) {
    uint32_t ra;
    asm volatile("mapa.shared::cluster.u32 %0, %1, %2;" : "=r"(ra) : "r"(laddr), "r"(rk));
    asm volatile("mbarrier.arrive.release.cluster.shared::cluster.b64 _, [%0];"
                 :: "r"(ra) : "memory");
}

__device__ __forceinline__ void mbar_wait_cluster(uint32_t addr, uint32_t parity) {
    asm volatile(
        "{\n\t"
        ".reg .pred P;\n\t"
        "WL%=:\n\t"
        "mbarrier.try_wait.parity.acquire.cluster.shared::cta.b64 P, [%0], %1, 0x989680;\n\t"
        "@P bra.uni WD%=;\n\t"
        "bra.uni WL%=;\n\t"
        "WD%=:\n\t"
        "}" :: "r"(addr), "r"(parity) : "memory");
}

// packed f32x2 fused multiply-add: d = a*b + d  (2 fp32 FMAs per instruction)
// NOTE: explicit 4-operand form ("=l" out + "l" d input) — the "+l" form with
// %3 in the template ICEs nvcc (operand index out of range).
__device__ __forceinline__ void ffma2(unsigned long long& d,
                                      unsigned long long a, unsigned long long b) {
    asm("fma.rn.f32x2 %0, %1, %2, %3;" : "=l"(d) : "l"(a), "l"(b), "l"(d));
}
__device__ __forceinline__ float f2sum(unsigned long long v) {
    float2 f = *reinterpret_cast<float2*>(&v);
    return f.x + f.y;
}
__device__ __forceinline__ unsigned long long packdup(float a) {
    unsigned long long d;
    unsigned int ai = __float_as_uint(a);
    asm("mov.b64 %0, {%1, %1};" : "=l"(d) : "r"(ai));
    return d;
}

__device__ __forceinline__ float sigf(float x) {
    return __fdividef(1.0f, 1.0f + __expf(-x));
}
__device__ __forceinline__ float tanh_fast(float x) {
    return 2.0f * sigf(2.0f * x) - 1.0f;
}

// ---------------------------------------------------------------------------
// Phase A: G0[t][b][row] = (bih0+bhh0)[row] + sum_{k<8} x[b][t][k]*Wih0[row][k]
// 16 (t,b) pairs per block; W rows + bias kept in registers. grid 2048, 256 thr.
// ---------------------------------------------------------------------------
__global__ void __launch_bounds__(256) phaseA_kernel(
    const float* __restrict__ x, const float* __restrict__ Wih0,
    const float* __restrict__ bih0, const float* __restrict__ bhh0,
    float* __restrict__ G)
{
    __shared__ float xs[16][8];
    int tid = threadIdx.x;
    int p0 = blockIdx.x * 16;

    float w[4][8];
    float bsv[4];
#pragma unroll
    for (int g = 0; g < 4; g++) {
        int r = tid + g * 256;
        const float4* wp = (const float4*)(Wih0 + (size_t)r * 8);
        float4 w0 = wp[0], w1 = wp[1];
        w[g][0] = w0.x; w[g][1] = w0.y; w[g][2] = w0.z; w[g][3] = w0.w;
        w[g][4] = w1.x; w[g][5] = w1.y; w[g][6] = w1.z; w[g][7] = w1.w;
        bsv[g] = bih0[r] + bhh0[r];
    }
    if (tid < 128) {
        int q = tid >> 3, k = tid & 7;
        int p = p0 + q;
        int b = p & 63, t = p >> 6;
        xs[q][k] = x[((size_t)b * 512 + t) * 8 + k];
    }
    __syncthreads();

    for (int q = 0; q < 16; q++) {
        size_t gb = (size_t)(p0 + q) * 1024;
#pragma unroll
        for (int g = 0; g < 4; g++) {
            float acc = bsv[g];
#pragma unroll
            for (int k = 0; k < 8; k++) acc = fmaf(w[g][k], xs[q][k], acc);
            G[gb + tid + g * 256] = acc;
        }
    }
}

// ---------------------------------------------------------------------------
// LSTM recurrence. 16 clusters x 8 CTAs (grid 128), 512 threads.
// Cluster cl owns batch rows [4cl,4cl+4). CTA rank owns 32 hidden units (128
// gate rows); Whh slice in registers as packed f32x2. h exchanged via DSMEM
// push + mbarrier handshake (expect=8 arrivals/step), double-buffered.
// ---------------------------------------------------------------------------
__global__ void __cluster_dims__(8, 1, 1) __launch_bounds__(512, 1)
lstm_recur_kernel(const float* __restrict__ G, const float* __restrict__ Whh,
                  float* __restrict__ hout, float* __restrict__ hsum, int dosum)
{
    // padded h layout: hk(k) = k + (k>>6)*4 -> kc chunks at float offsets 0,68,136,204
    __shared__ float hbuf[2][4][272];
    __shared__ float gsm[4][4][33];   // [gate][b][u]
    __shared__ __align__(8) unsigned long long mbar;

    int tid = threadIdx.x;
    int rank = blockIdx.x & 7;
    int cl = blockIdx.x >> 3;
    int row_local = tid >> 2;         // 0..127
    int kc = tid & 3;                 // 64-wide k-chunk
    int gate = row_local >> 5;        // 0..3
    int u = row_local & 31;
    int grow = gate * 256 + rank * 32 + u;

    // Whh slice into registers: 64 floats = 32 packed f32x2
    unsigned long long w[32];
    {
        const ulonglong2* wp = (const ulonglong2*)(Whh + (size_t)grow * 256 + kc * 64);
#pragma unroll
        for (int i = 0; i < 16; i++) { ulonglong2 v = wp[i]; w[2 * i] = v.x; w[2 * i + 1] = v.y; }
    }

    for (int i = tid; i < 4 * 272; i += 512) (&hbuf[0][0][0])[i] = 0.0f;

    uint32_t mbar_addr = (uint32_t)__cvta_generic_to_shared(&mbar);
    if (tid == 0)
        asm volatile("mbarrier.init.shared.b64 [%0], 8;" :: "r"(mbar_addr) : "memory");

    int bb = tid >> 5, ub = tid & 31;  // h-thread mapping (tid<128)
    float c = 0.0f, hs = 0.0f;
    uint32_t push0 = 0;
    {
        int k = rank * 32 + ub;
        int hk = k + ((k >> 6) << 2);
        push0 = (uint32_t)__cvta_generic_to_shared(&hbuf[0][bb & 3][hk]);
    }
    uint32_t bstride = (uint32_t)((char*)&hbuf[1][0][0] - (char*)&hbuf[0][0][0]);

    __syncthreads();
    cluster_sync_asm();   // all mbarriers initialized before any remote arrive

    const float* gbase = G + (size_t)(cl * 4) * 1024 + grow;
    float gin0 = 0, gin1 = 0, gin2 = 0, gin3 = 0;
    if (kc == 0) {
        gin0 = gbase[0]; gin1 = gbase[1024]; gin2 = gbase[2048]; gin3 = gbase[3072];
    }

    for (int t = 0; t < 512; t++) {
        int cur = t & 1;
        if (t > 0) mbar_wait_cluster(mbar_addr, (t + 1) & 1);

        // software-pipelined gate-input prefetch for t+1 (kc==0 lanes only)
        float ng0 = 0, ng1 = 0, ng2 = 0, ng3 = 0;
        if (kc == 0) {
            int tn = (t < 511) ? t + 1 : t;
            const float* gp = gbase + (size_t)tn * 65536;
            ng0 = gp[0]; ng1 = gp[1024]; ng2 = gp[2048]; ng3 = gp[3072];
        }

        unsigned long long acc[4][2];
#pragma unroll
        for (int b = 0; b < 4; b++) { acc[b][0] = 0ull; acc[b][1] = 0ull; }
#pragma unroll
        for (int b = 0; b < 4; b++) {
            const ulonglong2* hp = (const ulonglong2*)&hbuf[cur][b][kc * 68];
#pragma unroll
            for (int q = 0; q < 16; q++) {
                ulonglong2 h2 = hp[q];
                ffma2(acc[b][0], w[2 * q], h2.x);
                ffma2(acc[b][1], w[2 * q + 1], h2.y);
            }
        }
        float av[4];
#pragma unroll
        for (int b = 0; b < 4; b++) {
            float v = f2sum(acc[b][0]) + f2sum(acc[b][1]);
            v += __shfl_xor_sync(0xffffffffu, v, 1);
            v += __shfl_xor_sync(0xffffffffu, v, 2);
            av[b] = v;
        }
        if (kc == 0) {
            gsm[gate][0][u] = av[0] + gin0;
            gsm[gate][1][u] = av[1] + gin1;
            gsm[gate][2][u] = av[2] + gin2;
            gsm[gate][3][u] = av[3] + gin3;
        }
        gin0 = ng0; gin1 = ng1; gin2 = ng2; gin3 = ng3;
        __syncthreads();

        if (tid < 128) {
            float gi = gsm[0][bb][ub];
            float gf = gsm[1][bb][ub];
            float gg = gsm[2][bb][ub];
            float go = gsm[3][bb][ub];
            c = sigf(gf) * c + sigf(gi) * tanh_fast(gg);
            float h = sigf(go) * tanh_fast(c);
            hs += h;
            hout[((size_t)t * 64 + cl * 4 + bb) * 256 + rank * 32 + ub] = h;
            if (t < 511) {
                uint32_t pa = push0 + (uint32_t)(cur ^ 1) * bstride;
#pragma unroll
                for (int r = 0; r < 8; r++) st_dsmem(pa, (uint32_t)r, h);
            }
            asm volatile("bar.sync 1, 128;" ::: "memory");
            if (tid < 8 && t < 511) {
                asm volatile("fence.acq_rel.cluster;" ::: "memory");
                mbar_arrive_remote(mbar_addr, (uint32_t)tid);
            }
        }
    }
    if (dosum && tid < 128)
        hsum[(cl * 4 + bb) * 256 + rank * 32 + ub] = hs;
}

// ---------------------------------------------------------------------------
// fp32 NT GEMM (f32x2 inner): C[M=32768][N=1024] = A[M][256]@B[N][256]^T + bias
// 64x64 tile, BK=16, 256 threads, 4x4 per thread. grid (16, 512)
// ---------------------------------------------------------------------------
__global__ void __launch_bounds__(256) gemm_nt_kernel(
    const float* __restrict__ A, const float* __restrict__ B,
    const float* __restrict__ bi, const float* __restrict__ bh,
    float* __restrict__ C)
{
    __shared__ float As[16][68];
    __shared__ float Bs[16][68];
    int tid = threadIdx.x;
    int tx = tid & 15, ty = tid >> 4;
    int bm = blockIdx.y * 64, bn = blockIdx.x * 64;
    int lrow = tid >> 2, lkq = tid & 3;

    unsigned long long accp[4][2];
#pragma unroll
    for (int i = 0; i < 4; i++) { accp[i][0] = 0ull; accp[i][1] = 0ull; }

    for (int kk = 0; kk < 256; kk += 16) {
        float4 av = *(const float4*)(A + (size_t)(bm + lrow) * 256 + kk + lkq * 4);
        float4 bv = *(const float4*)(B + (size_t)(bn + lrow) * 256 + kk + lkq * 4);
        As[lkq * 4 + 0][lrow] = av.x; As[lkq * 4 + 1][lrow] = av.y;
        As[lkq * 4 + 2][lrow] = av.z; As[lkq * 4 + 3][lrow] = av.w;
        Bs[lkq * 4 + 0][lrow] = bv.x; Bs[lkq * 4 + 1][lrow] = bv.y;
        Bs[lkq * 4 + 2][lrow] = bv.z; Bs[lkq * 4 + 3][lrow] = bv.w;
        __syncthreads();
#pragma unroll
        for (int k = 0; k < 16; k++) {
            float4 a4 = *(const float4*)&As[k][tx * 4];
            ulonglong2 b2 = *(const ulonglong2*)&Bs[k][ty * 4];
            float am[4] = {a4.x, a4.y, a4.z, a4.w};
#pragma unroll
            for (int i = 0; i < 4; i++) {
                unsigned long long ai = packdup(am[i]);
                ffma2(accp[i][0], ai, b2.x);
                ffma2(accp[i][1], ai, b2.y);
            }
        }
        __syncthreads();
    }
#pragma unroll
    for (int i = 0; i < 4; i++) {
        size_t row = (size_t)(bm + tx * 4 + i) * 1024 + bn + ty * 4;
        float2 p0 = *reinterpret_cast<float2*>(&accp[i][0]);
        float2 p1 = *reinterpret_cast<float2*>(&accp[i][1]);
        int n = bn + ty * 4;
        C[row + 0] = p0.x + bi[n + 0] + bh[n + 0];
        C[row + 1] = p0.y + bi[n + 1] + bh[n + 1];
        C[row + 2] = p1.x + bi[n + 2] + bh[n + 2];
        C[row + 3] = p1.y + bi[n + 3] + bh[n + 3];
    }
}

// ---------------------------------------------------------------------------
// Phase E: m = hsum/512 ; a[b][n] = m[b].Wl1[n] + b1[n]   (n<100). grid 64.
// ---------------------------------------------------------------------------
__global__ void __launch_bounds__(128) phaseE_kernel(
    const float* __restrict__ hsum, const float* __restrict__ Wl1,
    const float* __restrict__ b1, float* __restrict__ a)
{
    int b = blockIdx.x;
    __shared__ float ms[256];
    for (int i = threadIdx.x; i < 256; i += 128)
        ms[i] = hsum[b * 256 + i] * (1.0f / 512.0f);
    __syncthreads();
    int n = threadIdx.x;
    if (n < 100) {
        const float* wr = Wl1 + (size_t)n * 256;
        float acc = b1[n];
        for (int k = 0; k < 256; k++) acc = fmaf(wr[k], ms[k], acc);
        a[b * 128 + n] = acc;
    }
}

// ---------------------------------------------------------------------------
// Phase F: y[b,t,n] = elu(h1[t,b].Wr1[n] + a[b][n]); chunked sum_t, y at 511.
// grid (8 chunks, 64 b), 512 thr; n = tid/4, kc = tid%4.
// ---------------------------------------------------------------------------
__global__ void __launch_bounds__(512) phaseF_kernel(
    const float* __restrict__ h1, const float* __restrict__ Wr1,
    const float* __restrict__ a, float* __restrict__ ypart,
    float* __restrict__ y511)
{
    int chunk = blockIdx.x;
    int b = blockIdx.y;
    int tid = threadIdx.x;
    int n = tid >> 2, kc = tid & 3;
    bool act = (n < 100);

    float w[64];
    if (act) {
        const float4* wp4 = (const float4*)(Wr1 + (size_t)n * 256 + kc * 64);
        float4* w4 = (float4*)w;
#pragma unroll
        for (int i = 0; i < 16; i++) w4[i] = wp4[i];
    }
    float ab = act ? a[b * 128 + n] : 0.0f;

    __shared__ float hsm[256];
    float acc = 0.0f;
    for (int tt = 0; tt < 64; tt++) {
        int t = chunk * 64 + tt;
        if (tid < 64)
            ((float4*)hsm)[tid] = ((const float4*)(h1 + ((size_t)t * 64 + b) * 256))[tid];
        __syncthreads();
        float d = 0.0f;
        if (act) {
            const float4* hp = (const float4*)&hsm[kc * 64];
#pragma unroll
            for (int q = 0; q < 16; q++) {
                float4 h4 = hp[q];
                d = fmaf(w[4 * q + 0], h4.x, d);
                d = fmaf(w[4 * q + 1], h4.y, d);
                d = fmaf(w[4 * q + 2], h4.z, d);
                d = fmaf(w[4 * q + 3], h4.w, d);
            }
        }
        d += __shfl_xor_sync(0xffffffffu, d, 1);
        d += __shfl_xor_sync(0xffffffffu, d, 2);
        if (act && kc == 0) {
            float p = d + ab;
            float y = (p > 0.0f) ? p : expm1f(p);
            acc += y;
            if (t == 511) y511[b * 128 + n] = y;
        }
        __syncthreads();
    }
    if (act && kc == 0) ypart[(chunk * 64 + b) * 128 + n] = acc;
}

// ---------------------------------------------------------------------------
// Phase G: m1 = (sum chunks)/512 ; s[b][d] = m1.Wl2[d] + b2[d] + y511.Wr2[d]
// ---------------------------------------------------------------------------
__global__ void __launch_bounds__(128) phaseG_kernel(
    const float* __restrict__ ypart, const float* __restrict__ y511,
    const float* __restrict__ Wl2, const float* __restrict__ b2,
    const float* __restrict__ Wr2, float* __restrict__ s)
{
    int b = blockIdx.x;
    int tid = threadIdx.x;
    __shared__ float m1[100], yl[100];
    if (tid < 100) {
        float t = 0.0f;
        for (int c2 = 0; c2 < 8; c2++) t += ypart[(c2 * 64 + b) * 128 + tid];
        m1[tid] = t * (1.0f / 512.0f);
        yl[tid] = y511[b * 128 + tid];
    }
    __syncthreads();
    const float* wl = Wl2 + (size_t)tid * 100;
    const float* wr = Wr2 + (size_t)tid * 100;
    float acc = b2[tid];
    for (int n = 0; n < 100; n++) {
        acc = fmaf(m1[n], wl[n], acc);
        acc = fmaf(yl[n], wr[n], acc);
    }
    s[b * 128 + tid] = acc;
}

// ---------------------------------------------------------------------------
// Phase H: z = relu(s.Wfc1 + bfc1); pred = z.Wfc2 + bfc2. grid (8,64), 64 thr.
// ---------------------------------------------------------------------------
__global__ void __launch_bounds__(64) phaseH_kernel(
    const float* __restrict__ s, const float* __restrict__ Wfc1,
    const float* __restrict__ bfc1, const float* __restrict__ Wfc2,
    const float* __restrict__ bfc2, float* __restrict__ out)
{
    int k = blockIdx.x;
    int b = blockIdx.y;
    int o = threadIdx.x;
    __shared__ float ss[128], zz[64];
    ((float2*)ss)[o] = ((const float2*)(s + b * 128))[o];
    __syncthreads();
    {
        const float* w = Wfc1 + ((size_t)k * 64 + o) * 128;
        float acc = bfc1[k * 64 + o];
        for (int d = 0; d < 128; d++) acc = fmaf(w[d], ss[d], acc);
        zz[o] = (acc > 0.0f) ? acc : 0.0f;
    }
    __syncthreads();
    if (o < 24) {
        const float* w2 = Wfc2 + ((size_t)k * 24 + o) * 64;
        float acc = bfc2[k * 24 + o];
        for (int d = 0; d < 64; d++) acc = fmaf(w2[d], zz[d], acc);
        out[((size_t)k * 64 + b) * 24 + o] = acc;
    }
}

// ---------------------------------------------------------------------------
extern "C" void kernel_launch(void* const* d_in, const int* in_sizes, int n_in,
                              void* d_out, int out_size)
{
    const float* x    = (const float*)d_in[0];
    const float* Wih0 = (const float*)d_in[1];
    const float* Whh0 = (const float*)d_in[2];
    const float* bih0 = (const float*)d_in[3];
    const float* bhh0 = (const float*)d_in[4];
    const float* Wih1 = (const float*)d_in[5];
    const float* Whh1 = (const float*)d_in[6];
    const float* bih1 = (const float*)d_in[7];
    const float* bhh1 = (const float*)d_in[8];
    const float* Wl1  = (const float*)d_in[9];
    const float* Wr1  = (const float*)d_in[10];
    const float* b1   = (const float*)d_in[11];
    const float* Wl2  = (const float*)d_in[12];
    const float* Wr2  = (const float*)d_in[13];
    const float* b2   = (const float*)d_in[14];
    const float* Wfc1 = (const float*)d_in[15];
    const float* bfc1 = (const float*)d_in[16];
    const float* Wfc2 = (const float*)d_in[17];
    const float* bfc2 = (const float*)d_in[18];

    float *G, *h0, *h1, *hsum, *a, *ypart, *y511, *s;
    cudaGetSymbolAddress((void**)&G, g_G);
    cudaGetSymbolAddress((void**)&h0, g_h0);
    cudaGetSymbolAddress((void**)&h1, g_h1);
    cudaGetSymbolAddress((void**)&hsum, g_hsum);
    cudaGetSymbolAddress((void**)&a, g_a);
    cudaGetSymbolAddress((void**)&ypart, g_ypart);
    cudaGetSymbolAddress((void**)&y511, g_y511);
    cudaGetSymbolAddress((void**)&s, g_s);

    phaseA_kernel<<<2048, 256>>>(x, Wih0, bih0, bhh0, G);
    lstm_recur_kernel<<<128, 512>>>(G, Whh0, h0, hsum, 0);
    gemm_nt_kernel<<<dim3(16, 512), 256>>>(h0, Wih1, bih1, bhh1, G);
    lstm_recur_kernel<<<128, 512>>>(G, Whh1, h1, hsum, 1);
    phaseE_kernel<<<64, 128>>>(hsum, Wl1, b1, a);
    phaseF_kernel<<<dim3(8, 64), 512>>>(h1, Wr1, a, ypart, y511);
    phaseG_kernel<<<64, 128>>>(ypart, y511, Wl2, b2, Wr2, s);
    phaseH_kernel<<<dim3(8, 64), 64>>>(s, Wfc1, bfc1, Wfc2, bfc2, (float*)d_out);
}